// round 15
// baseline (speedup 1.0000x reference)
#include <cuda_runtime.h>

// Projection: per row i of x[N,128]:
//   sq = sum(x_i^2); s = (sq-1)/(sq+1); out_i = [(1-s)*x_i, s]  -> out[N,129]
// with (1-s) = 2/(1+sq).
//
// Converged flat-grid config, HBM-bound at ~6.75TB/s (85% of spec).
// Evidence log:
//  R1: misaligned 516B-stride row stores merge fully in L2
//  R2: smem-staged aligned stores -18%;  R11: persistent grid -17%
//  R3: MLP 4->16 front-batched scalar loads +7% DRAM (winner)
//  R4/R10: 8 rows/warp neutral;  R5: float4 loads slightly worse
//  R9: __stcs evict-first stores +1.6% DRAM (winner)
//  R12: tail-store reorder neutral (stability confirmed at 156.4us)
// R13 final A/B: __ldcg loads (L1-bypass, L2-only). Streaming reads have
// zero reuse, so L1 allocation only burns L1tex queue slots shared with
// the store path.

#define D 128
#define THREADS 256
#define WARPS (THREADS / 32)
#define ROWS_PER_WARP 4
#define ROWS_PER_BLOCK (WARPS * ROWS_PER_WARP)   // 32

__global__ void __launch_bounds__(THREADS) projection_kernel(
    const float* __restrict__ x, float* __restrict__ out)
{
    const int warp = threadIdx.x >> 5;
    const int lane = threadIdx.x & 31;
    const long long row0 = (long long)blockIdx.x * ROWS_PER_BLOCK
                         + (long long)warp * ROWS_PER_WARP;

    const float* __restrict__ xr = x + row0 * D + lane;

    // Front-batched, fully coalesced L1-bypass loads: 16 x LDG.32.CG
    float v[ROWS_PER_WARP][4];
    #pragma unroll
    for (int r = 0; r < ROWS_PER_WARP; r++)
        #pragma unroll
        for (int c = 0; c < 4; c++)
            v[r][c] = __ldcg(xr + r * D + c * 32);

    float sq[ROWS_PER_WARP];
    #pragma unroll
    for (int r = 0; r < ROWS_PER_WARP; r++)
        sq[r] = v[r][0] * v[r][0] + v[r][1] * v[r][1]
              + v[r][2] * v[r][2] + v[r][3] * v[r][3];

    // Interleaved warp reductions; afterwards every lane holds all sq[r]
    #pragma unroll
    for (int off = 16; off > 0; off >>= 1)
        #pragma unroll
        for (int r = 0; r < ROWS_PER_WARP; r++)
            sq[r] += __shfl_xor_sync(0xFFFFFFFFu, sq[r], off);

    // Tail scalars: lane r stores s for row (row0 + r) — one STG, 4 lanes.
    if (lane < ROWS_PER_WARP) {
        const float sql = sq[lane];
        __stcs(out + (row0 + lane) * (D + 1) + D, (sql - 1.0f) / (1.0f + sql));
    }

    #pragma unroll
    for (int r = 0; r < ROWS_PER_WARP; r++) {
        const float inv   = 1.0f / (1.0f + sq[r]);
        const float scale = 2.0f * inv;        // = 1 - s

        float* __restrict__ orow = out + (row0 + r) * (D + 1);
        #pragma unroll
        for (int c = 0; c < 4; c++)
            __stcs(orow + lane + c * 32, scale * v[r][c]);
    }
}

extern "C" void kernel_launch(void* const* d_in, const int* in_sizes, int n_in,
                              void* d_out, int out_size)
{
    const float* x = (const float*)d_in[0];
    float* out = (float*)d_out;
    const int n_rows = in_sizes[0] / D;                    // 1048576
    const int blocks = n_rows / ROWS_PER_BLOCK;            // exact: 32768
    projection_kernel<<<blocks, THREADS>>>(x, out);
}

// round 17
// speedup vs baseline: 1.0063x; 1.0063x over previous
#include <cuda_runtime.h>

// Projection: per row i of x[N,128]:
//   sq = sum(x_i^2); s = (sq-1)/(sq+1); out_i = [(1-s)*x_i, s]  -> out[N,129]
// with (1-s) = 2/(1+sq).
//
// FINAL kernel — converged flat-grid config, HBM-bound at ~6.74TB/s
// (85% of spec; practical ceiling for a 50/50 r/w stream with 516B-stride
// write rows). Full measured knob matrix across R1-R15:
//  R1:  misaligned row stores merge fully in L2 (traffic == payload)
//  R2:  smem-staged aligned stores: -18%
//  R3:  MLP 4->16 front-batched scalar __ldcs loads: +7% DRAM  [KEPT]
//  R4/R10: 8 rows/warp: neutral
//  R5:  float4 loads: slightly worse L1tex queueing than 4x LDG.32
//  R9:  __stcs evict-first stores: +1.6% DRAM               [KEPT]
//  R11: persistent grid: -17% (loop serializes per-warp MLP)
//  R12: tail-store reorder: neutral
//  R13: __ldcg L1-bypass loads: slightly worse than .cs
// Residual 15% of spec = DRAM r/w turnaround + partial-sector physics.

#define D 128
#define THREADS 256
#define WARPS (THREADS / 32)
#define ROWS_PER_WARP 4
#define ROWS_PER_BLOCK (WARPS * ROWS_PER_WARP)   // 32

__global__ void __launch_bounds__(THREADS) projection_kernel(
    const float* __restrict__ x, float* __restrict__ out)
{
    const int warp = threadIdx.x >> 5;
    const int lane = threadIdx.x & 31;
    const long long row0 = (long long)blockIdx.x * ROWS_PER_BLOCK
                         + (long long)warp * ROWS_PER_WARP;

    const float* __restrict__ xr = x + row0 * D + lane;

    // Front-batched, fully coalesced streaming loads: 16 x LDG.32.CS
    float v[ROWS_PER_WARP][4];
    #pragma unroll
    for (int r = 0; r < ROWS_PER_WARP; r++)
        #pragma unroll
        for (int c = 0; c < 4; c++)
            v[r][c] = __ldcs(xr + r * D + c * 32);

    float sq[ROWS_PER_WARP];
    #pragma unroll
    for (int r = 0; r < ROWS_PER_WARP; r++)
        sq[r] = v[r][0] * v[r][0] + v[r][1] * v[r][1]
              + v[r][2] * v[r][2] + v[r][3] * v[r][3];

    // Interleaved warp reductions; afterwards every lane holds all sq[r]
    #pragma unroll
    for (int off = 16; off > 0; off >>= 1)
        #pragma unroll
        for (int r = 0; r < ROWS_PER_WARP; r++)
            sq[r] += __shfl_xor_sync(0xFFFFFFFFu, sq[r], off);

    #pragma unroll
    for (int r = 0; r < ROWS_PER_WARP; r++) {
        const float inv   = 1.0f / (1.0f + sq[r]);
        const float scale = 2.0f * inv;        // = 1 - s

        float* __restrict__ orow = out + (row0 + r) * (D + 1);
        #pragma unroll
        for (int c = 0; c < 4; c++)
            __stcs(orow + lane + c * 32, scale * v[r][c]);
    }

    // Tail scalars: lane r stores s for row (row0 + r) — one STG, 4 active lanes.
    if (lane < ROWS_PER_WARP) {
        const float sql = sq[lane];
        __stcs(out + (row0 + lane) * (D + 1) + D, (sql - 1.0f) / (1.0f + sql));
    }
}

extern "C" void kernel_launch(void* const* d_in, const int* in_sizes, int n_in,
                              void* d_out, int out_size)
{
    const float* x = (const float*)d_in[0];
    float* out = (float*)d_out;
    const int n_rows = in_sizes[0] / D;                    // 1048576
    const int blocks = n_rows / ROWS_PER_BLOCK;            // exact: 32768
    projection_kernel<<<blocks, THREADS>>>(x, out);
}